// round 1
// baseline (speedup 1.0000x reference)
#include <cuda_runtime.h>
#include <math.h>

#define D_MODEL 2048
#define NUM_HEADS 16
#define D_KV 128
#define N_LORA 4
#define RANK 16
#define BATCH 2
#define SEQ 2048
#define M_TOK (BATCH * SEQ) /* 4096 */

// ---------------- scratch (static device globals; no allocations) ----------------
__device__ float g_Q[M_TOK * D_MODEL];
__device__ float g_K[M_TOK * D_MODEL];
__device__ float g_V[M_TOK * D_MODEL];
__device__ float g_AO[M_TOK * D_MODEL];
__device__ float g_lowQ[M_TOK * RANK];
__device__ float g_lowK[M_TOK * RANK];
__device__ float g_lowV[M_TOK * RANK];
__device__ float g_lowO[M_TOK * RANK];

__device__ __forceinline__ int adapter_id(const int* __restrict__ starts, int b) {
    int cnt = 0;
#pragma unroll
    for (int i = 0; i < N_LORA; i++) cnt += (starts[i] <= b) ? 1 : 0;
    int id = cnt - 1;
    id = id < 0 ? 0 : id;
    id = id > (N_LORA - 1) ? (N_LORA - 1) : id;
    return id;
}

// ---------------- LoRA low-rank projection: low[m,r] = sum_d X[m,d]*A[id,r,d] ----------------
__global__ __launch_bounds__(128) void low_kernel(
    const float* __restrict__ X, const float* __restrict__ A,
    const int* __restrict__ starts, float* __restrict__ low)
{
    __shared__ float xs[D_MODEL];
    __shared__ float part[128];
    int m = blockIdx.x;
    int b = m / SEQ;
    int id = adapter_id(starts, b);
    const float* xrow = X + (size_t)m * D_MODEL;
    for (int i = threadIdx.x; i < D_MODEL / 4; i += 128)
        ((float4*)xs)[i] = ((const float4*)xrow)[i];
    __syncthreads();

    int r = threadIdx.x >> 3;   // 0..15
    int seg = threadIdx.x & 7;  // 0..7, each covers 256 elements
    const float* arow = A + ((size_t)id * RANK + r) * D_MODEL + seg * 256;
    const float* xseg = xs + seg * 256;
    float acc = 0.f;
#pragma unroll 8
    for (int d = 0; d < 256; d++) acc += xseg[d] * arow[d];
    part[threadIdx.x] = acc;
    __syncthreads();
    if (seg == 0) {
        float s = 0.f;
#pragma unroll
        for (int i = 0; i < 8; i++) s += part[(r << 3) + i];
        low[(size_t)m * RANK + r] = s;
    }
}

// ---------------- fused GEMM + LoRA epilogue ----------------
// Y[m,n] = sum_k X[m,k]*W[n,k] + sum_r low[m,r]*Bl[id(m), n, r]
// Tile 128x128, K-tile 8, 256 threads, 8x8 micro-tile, register-prefetched gmem loads.
#define GT 128
#define GKT 8
__global__ __launch_bounds__(256) void gemm_lora_kernel(
    const float* __restrict__ X, const float* __restrict__ W,
    const float* __restrict__ low, const float* __restrict__ Bl,
    const int* __restrict__ starts, float* __restrict__ Y)
{
    __shared__ float As[GKT][GT];
    __shared__ float Bs[GKT][GT];
    __shared__ float lows[GT][RANK + 1];
    __shared__ float Bls[GT][RANK + 1];

    int tid = threadIdx.x;
    int bm = blockIdx.y * GT;
    int bn = blockIdx.x * GT;
    int tx = tid & 15, ty = tid >> 4;

    float acc[8][8];
#pragma unroll
    for (int i = 0; i < 8; i++)
#pragma unroll
        for (int j = 0; j < 8; j++) acc[i][j] = 0.f;

    int lr = tid >> 1;
    int lk = (tid & 1) << 2;
    const float* Xp = X + (size_t)(bm + lr) * D_MODEL + lk;
    const float* Wp = W + (size_t)(bn + lr) * D_MODEL + lk;

    float4 a = *(const float4*)(Xp);
    float4 bv = *(const float4*)(Wp);

    for (int k0 = 0; k0 < D_MODEL; k0 += GKT) {
        As[lk + 0][lr] = a.x; As[lk + 1][lr] = a.y; As[lk + 2][lr] = a.z; As[lk + 3][lr] = a.w;
        Bs[lk + 0][lr] = bv.x; Bs[lk + 1][lr] = bv.y; Bs[lk + 2][lr] = bv.z; Bs[lk + 3][lr] = bv.w;
        __syncthreads();
        // prefetch next tile while computing this one
        if (k0 + GKT < D_MODEL) {
            a = *(const float4*)(Xp + k0 + GKT);
            bv = *(const float4*)(Wp + k0 + GKT);
        }
#pragma unroll
        for (int kk = 0; kk < GKT; kk++) {
            float af[8], bf[8];
            *(float4*)&af[0] = *(float4*)&As[kk][ty * 8];
            *(float4*)&af[4] = *(float4*)&As[kk][ty * 8 + 4];
            *(float4*)&bf[0] = *(float4*)&Bs[kk][tx * 8];
            *(float4*)&bf[4] = *(float4*)&Bs[kk][tx * 8 + 4];
#pragma unroll
            for (int i = 0; i < 8; i++)
#pragma unroll
                for (int j = 0; j < 8; j++)
                    acc[i][j] += af[i] * bf[j];
        }
        __syncthreads();
    }

    // ---- LoRA epilogue ----
    int id = adapter_id(starts, bm / SEQ);
    for (int i = tid; i < GT * RANK / 4; i += 256) {
        int row = i >> 2, rr = (i & 3) << 2;
        float4 t1 = *(const float4*)&low[(size_t)(bm + row) * RANK + rr];
        lows[row][rr + 0] = t1.x; lows[row][rr + 1] = t1.y;
        lows[row][rr + 2] = t1.z; lows[row][rr + 3] = t1.w;
        float4 t2 = *(const float4*)&Bl[((size_t)id * D_MODEL + bn + row) * RANK + rr];
        Bls[row][rr + 0] = t2.x; Bls[row][rr + 1] = t2.y;
        Bls[row][rr + 2] = t2.z; Bls[row][rr + 3] = t2.w;
    }
    __syncthreads();
#pragma unroll
    for (int r = 0; r < RANK; r++) {
        float lv[8], bw[8];
#pragma unroll
        for (int i = 0; i < 8; i++) lv[i] = lows[ty * 8 + i][r];
#pragma unroll
        for (int j = 0; j < 8; j++) bw[j] = Bls[tx * 8 + j][r];
#pragma unroll
        for (int i = 0; i < 8; i++)
#pragma unroll
            for (int j = 0; j < 8; j++) acc[i][j] += lv[i] * bw[j];
    }
#pragma unroll
    for (int i = 0; i < 8; i++) {
        float* yp = Y + (size_t)(bm + ty * 8 + i) * D_MODEL + bn + tx * 8;
        *(float4*)yp = *(float4*)&acc[i][0];
        *(float4*)(yp + 4) = *(float4*)&acc[i][4];
    }
}

// ---------------- RoPE (in-place on [B,S,D_MODEL], per-head interleaved pairs) ----------------
__global__ __launch_bounds__(256) void rope_kernel(float* __restrict__ T) {
    int idx = blockIdx.x * blockDim.x + threadIdx.x;
    if (idx >= BATCH * SEQ * NUM_HEADS * (D_KV / 2)) return;
    int jj = idx & 63;
    int h = (idx >> 6) & (NUM_HEADS - 1);
    int s = (idx >> 10) & (SEQ - 1);
    int b = idx >> 21;
    float freq = powf(10000.f, -(float)(2 * jj) / (float)D_KV);
    float ang = (float)s * freq;
    float sn, cs;
    sincosf(ang, &sn, &cs);
    size_t p = ((size_t)(b * SEQ + s)) * D_MODEL + h * D_KV + 2 * jj;
    float x1 = T[p], x2 = T[p + 1];
    T[p]     = x1 * cs - x2 * sn;
    T[p + 1] = x1 * sn + x2 * cs;
}

// ---------------- causal flash attention (fp32) ----------------
// Q-tile 64, K-tile 64, D=128. 256 threads.
#define AQT 64
#define AKT 64
#define KTS_STRIDE 65  /* pad to break STS bank conflicts on the transpose */
#define SS_STRIDE 65

#define ATTN_SMEM_FLOATS (AQT * D_KV + D_KV * KTS_STRIDE + AKT * D_KV + AQT * SS_STRIDE + 3 * AQT)
#define ATTN_SMEM_BYTES (ATTN_SMEM_FLOATS * 4)

__global__ __launch_bounds__(256) void attn_kernel(
    const float* __restrict__ Q, const float* __restrict__ K,
    const float* __restrict__ V, float* __restrict__ O)
{
    extern __shared__ float sm[];
    float* Qs = sm;                          // [64][128]
    float* Kts = Qs + AQT * D_KV;            // [128][65] transposed
    float* Vs = Kts + D_KV * KTS_STRIDE;     // [64][128]
    float* Ss = Vs + AKT * D_KV;             // [64][65]
    float* rowm = Ss + AQT * SS_STRIDE;
    float* rowl = rowm + AQT;
    float* rowc = rowl + AQT;

    int tid = threadIdx.x;
    int qt = blockIdx.x, h = blockIdx.y, b = blockIdx.z;
    int q0 = qt * AQT;
    const size_t base = ((size_t)b * SEQ) * D_MODEL + (size_t)h * D_KV;

    // load Q tile (natural layout, coalesced)
    for (int i = tid; i < AQT * D_KV / 4; i += 256) {
        int q = (i * 4) / D_KV, d = (i * 4) % D_KV;
        *(float4*)&Qs[q * D_KV + d] =
            *(const float4*)&Q[base + (size_t)(q0 + q) * D_MODEL + d];
    }
    if (tid < AQT) { rowm[tid] = -1e30f; rowl[tid] = 0.f; }

    int tx = tid & 15, ty = tid >> 4;
    float o_acc[4][8];
#pragma unroll
    for (int i = 0; i < 4; i++)
#pragma unroll
        for (int j = 0; j < 8; j++) o_acc[i][j] = 0.f;

    const float scale = 0.0883883476483184f; // 1/sqrt(128)

    for (int j = 0; j <= qt; j++) {
        int k0 = j * AKT;
        __syncthreads(); // protect Kts/Vs/Ss against prev-iter readers (and Q load on iter 0)

        // load K transposed + V natural
        for (int i = tid; i < AKT * D_KV / 4; i += 256) {
            int kk = (i * 4) / D_KV, d = (i * 4) % D_KV;
            float4 kv = *(const float4*)&K[base + (size_t)(k0 + kk) * D_MODEL + d];
            Kts[(d + 0) * KTS_STRIDE + kk] = kv.x;
            Kts[(d + 1) * KTS_STRIDE + kk] = kv.y;
            Kts[(d + 2) * KTS_STRIDE + kk] = kv.z;
            Kts[(d + 3) * KTS_STRIDE + kk] = kv.w;
            *(float4*)&Vs[kk * D_KV + d] =
                *(const float4*)&V[base + (size_t)(k0 + kk) * D_MODEL + d];
        }
        __syncthreads();

        // S = Q K^T  (4x4 micro-tile per thread)
        float s_acc[4][4];
#pragma unroll
        for (int i = 0; i < 4; i++)
#pragma unroll
            for (int jj = 0; jj < 4; jj++) s_acc[i][jj] = 0.f;

        for (int d = 0; d < D_KV; d++) {
            float af[4], bf[4];
#pragma unroll
            for (int i = 0; i < 4; i++) af[i] = Qs[(ty * 4 + i) * D_KV + d];
#pragma unroll
            for (int jj = 0; jj < 4; jj++) bf[jj] = Kts[d * KTS_STRIDE + tx * 4 + jj];
#pragma unroll
            for (int i = 0; i < 4; i++)
#pragma unroll
                for (int jj = 0; jj < 4; jj++) s_acc[i][jj] += af[i] * bf[jj];
        }
        // scale + causal mask + write to smem
#pragma unroll
        for (int i = 0; i < 4; i++) {
            int qg = q0 + ty * 4 + i;
#pragma unroll
            for (int jj = 0; jj < 4; jj++) {
                int kg = k0 + tx * 4 + jj;
                Ss[(ty * 4 + i) * SS_STRIDE + tx * 4 + jj] =
                    (kg <= qg) ? s_acc[i][jj] * scale : -1e30f;
            }
        }
        __syncthreads();

        // online softmax per row (one thread per row)
        if (tid < AQT) {
            float mold = rowm[tid];
            float mx = mold;
            float* srow = Ss + tid * SS_STRIDE;
            for (int k = 0; k < AKT; k++) mx = fmaxf(mx, srow[k]);
            float c = __expf(mold - mx);
            float l = rowl[tid] * c;
            for (int k = 0; k < AKT; k++) {
                float p = __expf(srow[k] - mx);
                srow[k] = p;
                l += p;
            }
            rowm[tid] = mx; rowl[tid] = l; rowc[tid] = c;
        }
        __syncthreads();

        // O = O*c + P V  (4x8 micro-tile per thread)
#pragma unroll
        for (int i = 0; i < 4; i++) {
            float c = rowc[ty * 4 + i];
#pragma unroll
            for (int jj = 0; jj < 8; jj++) o_acc[i][jj] *= c;
        }
        for (int k = 0; k < AKT; k++) {
            float bf[8];
            *(float4*)&bf[0] = *(float4*)&Vs[k * D_KV + tx * 8];
            *(float4*)&bf[4] = *(float4*)&Vs[k * D_KV + tx * 8 + 4];
#pragma unroll
            for (int i = 0; i < 4; i++) {
                float av = Ss[(ty * 4 + i) * SS_STRIDE + k];
#pragma unroll
                for (int jj = 0; jj < 8; jj++) o_acc[i][jj] += av * bf[jj];
            }
        }
    }

    // finalize + write out (attn output back in [B,S,D_MODEL] layout)
#pragma unroll
    for (int i = 0; i < 4; i++) {
        float inv = 1.f / rowl[ty * 4 + i];
        float buf[8];
#pragma unroll
        for (int jj = 0; jj < 8; jj++) buf[jj] = o_acc[i][jj] * inv;
        float* op = O + base + (size_t)(q0 + ty * 4 + i) * D_MODEL + tx * 8;
        *(float4*)op = *(float4*)&buf[0];
        *(float4*)(op + 4) = *(float4*)&buf[4];
    }
}

// ---------------- launch ----------------
extern "C" void kernel_launch(void* const* d_in, const int* in_sizes, int n_in,
                              void* d_out, int out_size)
{
    const float* x      = (const float*)d_in[0];
    const int* starts   = (const int*)d_in[1];
    const float* Wq     = (const float*)d_in[2];
    const float* Aq     = (const float*)d_in[3];
    const float* Bq     = (const float*)d_in[4];
    const float* Wk     = (const float*)d_in[5];
    const float* Ak     = (const float*)d_in[6];
    const float* Bk     = (const float*)d_in[7];
    const float* Wv     = (const float*)d_in[8];
    const float* Av     = (const float*)d_in[9];
    const float* Bv     = (const float*)d_in[10];
    const float* Wo     = (const float*)d_in[11];
    const float* Ao     = (const float*)d_in[12];
    const float* Bo     = (const float*)d_in[13];
    float* out = (float*)d_out;

    float *Qb, *Kb, *Vb, *AOb, *lq, *lk, *lv, *lo;
    cudaGetSymbolAddress((void**)&Qb, g_Q);
    cudaGetSymbolAddress((void**)&Kb, g_K);
    cudaGetSymbolAddress((void**)&Vb, g_V);
    cudaGetSymbolAddress((void**)&AOb, g_AO);
    cudaGetSymbolAddress((void**)&lq, g_lowQ);
    cudaGetSymbolAddress((void**)&lk, g_lowK);
    cudaGetSymbolAddress((void**)&lv, g_lowV);
    cudaGetSymbolAddress((void**)&lo, g_lowO);

    cudaFuncSetAttribute(attn_kernel, cudaFuncAttributeMaxDynamicSharedMemorySize,
                         ATTN_SMEM_BYTES);

    dim3 gg(D_MODEL / GT, M_TOK / GT);

    // low-rank projections for Q/K/V
    low_kernel<<<M_TOK, 128>>>(x, Aq, starts, lq);
    low_kernel<<<M_TOK, 128>>>(x, Ak, starts, lk);
    low_kernel<<<M_TOK, 128>>>(x, Av, starts, lv);

    // fused base GEMM + LoRA epilogue
    gemm_lora_kernel<<<gg, 256>>>(x, Wq, lq, Bq, starts, Qb);
    gemm_lora_kernel<<<gg, 256>>>(x, Wk, lk, Bk, starts, Kb);
    gemm_lora_kernel<<<gg, 256>>>(x, Wv, lv, Bv, starts, Vb);

    // RoPE on Q, K
    int npairs = BATCH * SEQ * NUM_HEADS * (D_KV / 2);
    rope_kernel<<<(npairs + 255) / 256, 256>>>(Qb);
    rope_kernel<<<(npairs + 255) / 256, 256>>>(Kb);

    // causal flash attention
    attn_kernel<<<dim3(SEQ / AQT, NUM_HEADS, BATCH), 256, ATTN_SMEM_BYTES>>>(Qb, Kb, Vb, AOb);

    // output projection with LoRA
    low_kernel<<<M_TOK, 128>>>(AOb, Ao, starts, lo);
    gemm_lora_kernel<<<gg, 256>>>(AOb, Wo, lo, Bo, starts, out);
}

// round 3
// speedup vs baseline: 1.6688x; 1.6688x over previous
#include <cuda_runtime.h>
#include <cuda_bf16.h>
#include <math.h>
#include <stdint.h>

#define D_MODEL 2048
#define NUM_HEADS 16
#define D_KV 128
#define N_LORA 4
#define RANK 16
#define BATCH 2
#define SEQ 2048
#define M_TOK (BATCH * SEQ) /* 4096 */

// ---------------- scratch (static device globals; no allocations) ----------------
__device__ float g_Q[M_TOK * D_MODEL];
__device__ float g_K[M_TOK * D_MODEL];
__device__ float g_V[M_TOK * D_MODEL];
__device__ float g_AO[M_TOK * D_MODEL];
__device__ float g_lowQ[M_TOK * RANK];
__device__ float g_lowK[M_TOK * RANK];
__device__ float g_lowV[M_TOK * RANK];
__device__ float g_lowO[M_TOK * RANK];

__device__ __forceinline__ int adapter_id(const int* __restrict__ starts, int b) {
    int cnt = 0;
#pragma unroll
    for (int i = 0; i < N_LORA; i++) cnt += (starts[i] <= b) ? 1 : 0;
    int id = cnt - 1;
    id = id < 0 ? 0 : id;
    id = id > (N_LORA - 1) ? (N_LORA - 1) : id;
    return id;
}

// ======================= helpers =======================
__device__ __forceinline__ uint32_t smem_u32(const void* p) {
    uint32_t a;
    asm("{ .reg .u64 t; cvta.to.shared.u64 t, %1; cvt.u32.u64 %0, t; }" : "=r"(a) : "l"(p));
    return a;
}
__device__ __forceinline__ uint32_t bfpack(__nv_bfloat16 a, __nv_bfloat16 b) {
    return (uint32_t)__bfloat16_as_ushort(a) | ((uint32_t)__bfloat16_as_ushort(b) << 16);
}
__device__ __forceinline__ void split4(float4 v, uint32_t& h0, uint32_t& h1,
                                       uint32_t& l0, uint32_t& l1) {
    __nv_bfloat16 hx = __float2bfloat16(v.x), hy = __float2bfloat16(v.y);
    __nv_bfloat16 hz = __float2bfloat16(v.z), hw = __float2bfloat16(v.w);
    __nv_bfloat16 lx = __float2bfloat16(v.x - __bfloat162float(hx));
    __nv_bfloat16 ly = __float2bfloat16(v.y - __bfloat162float(hy));
    __nv_bfloat16 lz = __float2bfloat16(v.z - __bfloat162float(hz));
    __nv_bfloat16 lw = __float2bfloat16(v.w - __bfloat162float(hw));
    h0 = bfpack(hx, hy); h1 = bfpack(hz, hw);
    l0 = bfpack(lx, ly); l1 = bfpack(lz, lw);
}

#define LDSM4(r, addr) \
    asm volatile("ldmatrix.sync.aligned.m8n8.x4.shared.b16 {%0,%1,%2,%3}, [%4];" \
                 : "=r"((r)[0]), "=r"((r)[1]), "=r"((r)[2]), "=r"((r)[3]) : "r"(addr))

#define MMA16816(c, a, b) \
    asm volatile("mma.sync.aligned.m16n8k16.row.col.f32.bf16.bf16.f32 " \
                 "{%0,%1,%2,%3}, {%4,%5,%6,%7}, {%8,%9}, {%0,%1,%2,%3};" \
                 : "+f"((c)[0]), "+f"((c)[1]), "+f"((c)[2]), "+f"((c)[3]) \
                 : "r"((a)[0]), "r"((a)[1]), "r"((a)[2]), "r"((a)[3]), \
                   "r"((b)[0]), "r"((b)[1]))

// ---------------- LoRA low-rank: low[m,r] = sum_d X[m,d]*A[id,r,d]; 4 rows/block ----------------
__global__ __launch_bounds__(128) void low_kernel(
    const float* __restrict__ X, const float* __restrict__ A,
    const int* __restrict__ starts, float* __restrict__ low)
{
    __shared__ float xs[4][D_MODEL];
    __shared__ float part[128][4];
    int m0 = blockIdx.x * 4;
    int id = adapter_id(starts, m0 / SEQ);
    const float* xrow = X + (size_t)m0 * D_MODEL;
    for (int i = threadIdx.x; i < 4 * D_MODEL / 4; i += 128)
        ((float4*)&xs[0][0])[i] = ((const float4*)xrow)[i];
    __syncthreads();

    int r = threadIdx.x >> 3;   // 0..15
    int seg = threadIdx.x & 7;  // 0..7 -> 256 elems each
    const float* arow = A + ((size_t)id * RANK + r) * D_MODEL + seg * 256;
    const float* x0 = &xs[0][seg * 256];
    const float* x1 = &xs[1][seg * 256];
    const float* x2 = &xs[2][seg * 256];
    const float* x3 = &xs[3][seg * 256];
    float a0 = 0.f, a1 = 0.f, a2 = 0.f, a3 = 0.f;
#pragma unroll 4
    for (int d = 0; d < 256; d++) {
        float a = arow[d];
        a0 += x0[d] * a; a1 += x1[d] * a; a2 += x2[d] * a; a3 += x3[d] * a;
    }
    part[threadIdx.x][0] = a0; part[threadIdx.x][1] = a1;
    part[threadIdx.x][2] = a2; part[threadIdx.x][3] = a3;
    __syncthreads();
    if (seg < 4) {
        float s = 0.f;
#pragma unroll
        for (int i = 0; i < 8; i++) s += part[(r << 3) + i][seg];
        low[(size_t)(m0 + seg) * RANK + r] = s;
    }
}

// ======================= mma.sync bf16-split GEMM + fused LoRA =======================
// Y[m,n] = sum_k X[m,k]*W[n,k] + sum_r low[m,r]*Bl[id,n,r]
// Block 128x128, K-tile 32, 8 warps (2m x 4n), warp tile 64x32.
// 3 passes: Ah*Bh + Ah*Bl + Al*Bh.  LoRA folded in as one extra k-step.
#define BM 128
#define BN 128
#define BK 32
#define ASTR 40 /* padded row stride (bf16 elems): conflict-free ldmatrix */

__global__ __launch_bounds__(256, 1) void gemm_lora_mma(
    const float* __restrict__ X, const float* __restrict__ W,
    const float* __restrict__ low, const float* __restrict__ Bl,
    const int* __restrict__ starts, float* __restrict__ Y)
{
    __shared__ __nv_bfloat16 sAh[BM][ASTR];
    __shared__ __nv_bfloat16 sAl[BM][ASTR];
    __shared__ __nv_bfloat16 sBh[BN][ASTR];
    __shared__ __nv_bfloat16 sBl[BN][ASTR];

    int tid = threadIdx.x;
    int lane = tid & 31;
    int wid = tid >> 5;
    int wm = wid >> 2;       // 0..1 -> 64-row slab
    int wn = wid & 3;        // 0..3 -> 32-col slab
    int bm = blockIdx.y * BM, bn = blockIdx.x * BN;
    int id = adapter_id(starts, bm / SEQ);

    float acc[4][4][4];
#pragma unroll
    for (int i = 0; i < 4; i++)
#pragma unroll
        for (int j = 0; j < 4; j++)
#pragma unroll
            for (int k = 0; k < 4; k++) acc[i][j][k] = 0.f;

    // loader: thread -> row (tid/2), 16-col half ((tid&1)*16)
    int lr = tid >> 1;
    int lc = (tid & 1) << 4;
    const float* Xp = X + (size_t)(bm + lr) * D_MODEL + lc;
    const float* Wp = W + (size_t)(bn + lr) * D_MODEL + lc;

    float4 pa[4], pb[4];
#pragma unroll
    for (int j = 0; j < 4; j++) {
        pa[j] = *(const float4*)(Xp + 4 * j);
        pb[j] = *(const float4*)(Wp + 4 * j);
    }

    // ldmatrix base addresses
    uint32_t uAh = smem_u32(&sAh[0][0]);
    uint32_t uAl = smem_u32(&sAl[0][0]);
    uint32_t uBh = smem_u32(&sBh[0][0]);
    uint32_t uBl = smem_u32(&sBl[0][0]);

    // A frag addr: row = wm*64 + mt*16 + (lane%16), col = k0 + 8*(lane/16)
    int a_row = wm * 64 + (lane & 15);
    int a_coladd = (lane >> 4) << 3;
    // B frag addr: row = wn*32 + half*16 + ((lane>>4)<<3) + (lane&7), col = k0 + ((lane>>3)&1)*8
    int b_row = wn * 32 + ((lane >> 4) << 3) + (lane & 7);
    int b_coladd = ((lane >> 3) & 1) << 3;

    const int NK = D_MODEL / BK; // 64

    for (int t = 0; t < NK; t++) {
        // convert + store current tile
#pragma unroll
        for (int j = 0; j < 4; j++) {
            uint32_t h0, h1, l0, l1;
            split4(pa[j], h0, h1, l0, l1);
            *(uint2*)&sAh[lr][lc + 4 * j] = make_uint2(h0, h1);
            *(uint2*)&sAl[lr][lc + 4 * j] = make_uint2(l0, l1);
            split4(pb[j], h0, h1, l0, l1);
            *(uint2*)&sBh[lr][lc + 4 * j] = make_uint2(h0, h1);
            *(uint2*)&sBl[lr][lc + 4 * j] = make_uint2(l0, l1);
        }
        __syncthreads();

        if (t + 1 < NK) {
#pragma unroll
            for (int j = 0; j < 4; j++) {
                pa[j] = *(const float4*)(Xp + (t + 1) * BK + 4 * j);
                pb[j] = *(const float4*)(Wp + (t + 1) * BK + 4 * j);
            }
        }

#pragma unroll
        for (int ks = 0; ks < 2; ks++) {
            int k0 = ks << 4;
            uint32_t ah[4][4], al[4][4], bh[4][2], bl[4][2];
#pragma unroll
            for (int mt = 0; mt < 4; mt++) {
                uint32_t off = (uint32_t)(((a_row + mt * 16) * ASTR + k0 + a_coladd) << 1);
                LDSM4(ah[mt], uAh + off);
                LDSM4(al[mt], uAl + off);
            }
#pragma unroll
            for (int half = 0; half < 2; half++) {
                uint32_t off = (uint32_t)(((b_row + half * 16) * ASTR + k0 + b_coladd) << 1);
                uint32_t rh[4], rl[4];
                LDSM4(rh, uBh + off);
                LDSM4(rl, uBl + off);
                bh[half * 2][0] = rh[0]; bh[half * 2][1] = rh[1];
                bh[half * 2 + 1][0] = rh[2]; bh[half * 2 + 1][1] = rh[3];
                bl[half * 2][0] = rl[0]; bl[half * 2][1] = rl[1];
                bl[half * 2 + 1][0] = rl[2]; bl[half * 2 + 1][1] = rl[3];
            }
#pragma unroll
            for (int mt = 0; mt < 4; mt++)
#pragma unroll
                for (int nt = 0; nt < 4; nt++) {
                    MMA16816(acc[mt][nt], ah[mt], bh[nt]);
                    MMA16816(acc[mt][nt], ah[mt], bl[nt]);
                    MMA16816(acc[mt][nt], al[mt], bh[nt]);
                }
        }
        __syncthreads();
    }

    // ---- LoRA extra k-step (rank 16 in cols 0..15) ----
    {
        if (tid < 128) {
            int row = tid;
#pragma unroll
            for (int j = 0; j < 4; j++) {
                float4 v = *(const float4*)(low + (size_t)(bm + row) * RANK + 4 * j);
                uint32_t h0, h1, l0, l1;
                split4(v, h0, h1, l0, l1);
                *(uint2*)&sAh[row][4 * j] = make_uint2(h0, h1);
                *(uint2*)&sAl[row][4 * j] = make_uint2(l0, l1);
            }
        } else {
            int row = tid - 128;
#pragma unroll
            for (int j = 0; j < 4; j++) {
                float4 v = *(const float4*)(Bl + ((size_t)id * D_MODEL + bn + row) * RANK + 4 * j);
                uint32_t h0, h1, l0, l1;
                split4(v, h0, h1, l0, l1);
                *(uint2*)&sBh[row][4 * j] = make_uint2(h0, h1);
                *(uint2*)&sBl[row][4 * j] = make_uint2(l0, l1);
            }
        }
        __syncthreads();

        uint32_t ah[4][4], al[4][4], bh[4][2], bl[4][2];
#pragma unroll
        for (int mt = 0; mt < 4; mt++) {
            uint32_t off = (uint32_t)(((a_row + mt * 16) * ASTR + a_coladd) << 1);
            LDSM4(ah[mt], uAh + off);
            LDSM4(al[mt], uAl + off);
        }
#pragma unroll
        for (int half = 0; half < 2; half++) {
            uint32_t off = (uint32_t)(((b_row + half * 16) * ASTR + b_coladd) << 1);
            uint32_t rh[4], rl[4];
            LDSM4(rh, uBh + off);
            LDSM4(rl, uBl + off);
            bh[half * 2][0] = rh[0]; bh[half * 2][1] = rh[1];
            bh[half * 2 + 1][0] = rh[2]; bh[half * 2 + 1][1] = rh[3];
            bl[half * 2][0] = rl[0]; bl[half * 2][1] = rl[1];
            bl[half * 2 + 1][0] = rl[2]; bl[half * 2 + 1][1] = rl[3];
        }
#pragma unroll
        for (int mt = 0; mt < 4; mt++)
#pragma unroll
            for (int nt = 0; nt < 4; nt++) {
                MMA16816(acc[mt][nt], ah[mt], bh[nt]);
                MMA16816(acc[mt][nt], ah[mt], bl[nt]);
                MMA16816(acc[mt][nt], al[mt], bh[nt]);
            }
    }

    // ---- epilogue: C frag -> global ----
#pragma unroll
    for (int mt = 0; mt < 4; mt++) {
#pragma unroll
        for (int nt = 0; nt < 4; nt++) {
            int row = bm + wm * 64 + mt * 16 + (lane >> 2);
            int col = bn + wn * 32 + nt * 8 + 2 * (lane & 3);
            *(float2*)&Y[(size_t)row * D_MODEL + col] =
                make_float2(acc[mt][nt][0], acc[mt][nt][1]);
            *(float2*)&Y[(size_t)(row + 8) * D_MODEL + col] =
                make_float2(acc[mt][nt][2], acc[mt][nt][3]);
        }
    }
}

// ---------------- RoPE (in-place on [B,S,D_MODEL], per-head interleaved pairs) ----------------
__global__ __launch_bounds__(256) void rope_kernel(float* __restrict__ T) {
    int idx = blockIdx.x * blockDim.x + threadIdx.x;
    if (idx >= BATCH * SEQ * NUM_HEADS * (D_KV / 2)) return;
    int jj = idx & 63;
    int h = (idx >> 6) & (NUM_HEADS - 1);
    int s = (idx >> 10) & (SEQ - 1);
    int b = idx >> 21;
    float freq = powf(10000.f, -(float)(2 * jj) / (float)D_KV);
    float ang = (float)s * freq;
    float sn, cs;
    sincosf(ang, &sn, &cs);
    size_t p = ((size_t)(b * SEQ + s)) * D_MODEL + h * D_KV + 2 * jj;
    float x1 = T[p], x2 = T[p + 1];
    T[p]     = x1 * cs - x2 * sn;
    T[p + 1] = x1 * sn + x2 * cs;
}

// ---------------- causal flash attention (fp32, register softmax) ----------------
#define AQT 64
#define AKT 64
#define KTS_STRIDE 65
#define SS_STRIDE 65
#define ATTN_SMEM_FLOATS (AQT * D_KV + D_KV * KTS_STRIDE + AKT * D_KV + AQT * SS_STRIDE)
#define ATTN_SMEM_BYTES (ATTN_SMEM_FLOATS * 4)

__global__ __launch_bounds__(256) void attn_kernel(
    const float* __restrict__ Q, const float* __restrict__ K,
    const float* __restrict__ V, float* __restrict__ O)
{
    extern __shared__ float sm[];
    float* Qs = sm;                          // [64][128]
    float* Kts = Qs + AQT * D_KV;            // [128][65] transposed
    float* Vs = Kts + D_KV * KTS_STRIDE;     // [64][128]
    float* Ss = Vs + AKT * D_KV;             // [64][65]

    int tid = threadIdx.x;
    int qt = blockIdx.x, h = blockIdx.y, b = blockIdx.z;
    int q0 = qt * AQT;
    const size_t base = ((size_t)b * SEQ) * D_MODEL + (size_t)h * D_KV;

    for (int i = tid; i < AQT * D_KV / 4; i += 256) {
        int q = (i * 4) / D_KV, d = (i * 4) % D_KV;
        *(float4*)&Qs[q * D_KV + d] =
            *(const float4*)&Q[base + (size_t)(q0 + q) * D_MODEL + d];
    }

    int tx = tid & 15, ty = tid >> 4;
    float o_acc[4][8];
#pragma unroll
    for (int i = 0; i < 4; i++)
#pragma unroll
        for (int j = 0; j < 8; j++) o_acc[i][j] = 0.f;

    float rm[4], rl[4];
#pragma unroll
    for (int i = 0; i < 4; i++) { rm[i] = -1e30f; rl[i] = 0.f; }

    const float scale = 0.0883883476483184f; // 1/sqrt(128)

    for (int j = 0; j <= qt; j++) {
        int k0 = j * AKT;
        __syncthreads();

        for (int i = tid; i < AKT * D_KV / 4; i += 256) {
            int kk = (i * 4) / D_KV, d = (i * 4) % D_KV;
            float4 kv = *(const float4*)&K[base + (size_t)(k0 + kk) * D_MODEL + d];
            Kts[(d + 0) * KTS_STRIDE + kk] = kv.x;
            Kts[(d + 1) * KTS_STRIDE + kk] = kv.y;
            Kts[(d + 2) * KTS_STRIDE + kk] = kv.z;
            Kts[(d + 3) * KTS_STRIDE + kk] = kv.w;
            *(float4*)&Vs[kk * D_KV + d] =
                *(const float4*)&V[base + (size_t)(k0 + kk) * D_MODEL + d];
        }
        __syncthreads();

        float s_acc[4][4];
#pragma unroll
        for (int i = 0; i < 4; i++)
#pragma unroll
            for (int jj = 0; jj < 4; jj++) s_acc[i][jj] = 0.f;

        for (int d = 0; d < D_KV; d++) {
            float af[4], bf[4];
#pragma unroll
            for (int i = 0; i < 4; i++) af[i] = Qs[(ty * 4 + i) * D_KV + d];
#pragma unroll
            for (int jj = 0; jj < 4; jj++) bf[jj] = Kts[d * KTS_STRIDE + tx * 4 + jj];
#pragma unroll
            for (int i = 0; i < 4; i++)
#pragma unroll
                for (int jj = 0; jj < 4; jj++) s_acc[i][jj] += af[i] * bf[jj];
        }

        // register-resident online softmax (shuffle over the 16-lane row group)
        float cfac[4];
#pragma unroll
        for (int i = 0; i < 4; i++) {
            int qg = q0 + ty * 4 + i;
            float sv[4];
#pragma unroll
            for (int jj = 0; jj < 4; jj++) {
                int kg = k0 + tx * 4 + jj;
                sv[jj] = (kg <= qg) ? s_acc[i][jj] * scale : -1e30f;
            }
            float mx = fmaxf(fmaxf(sv[0], sv[1]), fmaxf(sv[2], sv[3]));
#pragma unroll
            for (int dd = 1; dd < 16; dd <<= 1)
                mx = fmaxf(mx, __shfl_xor_sync(0xffffffffu, mx, dd));
            float mnew = fmaxf(rm[i], mx);
            float c = __expf(rm[i] - mnew);
            float sum = 0.f;
#pragma unroll
            for (int jj = 0; jj < 4; jj++) {
                float p = __expf(sv[jj] - mnew);
                Ss[(ty * 4 + i) * SS_STRIDE + tx * 4 + jj] = p;
                sum += p;
            }
#pragma unroll
            for (int dd = 1; dd < 16; dd <<= 1)
                sum += __shfl_xor_sync(0xffffffffu, sum, dd);
            rm[i] = mnew;
            rl[i] = rl[i] * c + sum;
            cfac[i] = c;
        }
        __syncthreads();

        // O = O*c + P V
#pragma unroll
        for (int i = 0; i < 4; i++) {
            float c = cfac[i];
#pragma unroll
            for (int jj = 0; jj < 8; jj++) o_acc[i][jj] *= c;
        }
        for (int k = 0; k < AKT; k++) {
            float bf[8];
            *(float4*)&bf[0] = *(float4*)&Vs[k * D_KV + tx * 8];
            *(float4*)&bf[4] = *(float4*)&Vs[k * D_KV + tx * 8 + 4];
#pragma unroll
            for (int i = 0; i < 4; i++) {
                float av = Ss[(ty * 4 + i) * SS_STRIDE + k];
#pragma unroll
                for (int jj = 0; jj < 8; jj++) o_acc[i][jj] += av * bf[jj];
            }
        }
    }

#pragma unroll
    for (int i = 0; i < 4; i++) {
        float inv = 1.f / rl[i];
        float buf[8];
#pragma unroll
        for (int jj = 0; jj < 8; jj++) buf[jj] = o_acc[i][jj] * inv;
        float* op = O + base + (size_t)(q0 + ty * 4 + i) * D_MODEL + tx * 8;
        *(float4*)op = *(float4*)&buf[0];
        *(float4*)(op + 4) = *(float4*)&buf[4];
    }
}

// ---------------- launch ----------------
extern "C" void kernel_launch(void* const* d_in, const int* in_sizes, int n_in,
                              void* d_out, int out_size)
{
    const float* x      = (const float*)d_in[0];
    const int* starts   = (const int*)d_in[1];
    const float* Wq     = (const float*)d_in[2];
    const float* Aq     = (const float*)d_in[3];
    const float* Bq     = (const float*)d_in[4];
    const float* Wk     = (const float*)d_in[5];
    const float* Ak     = (const float*)d_in[6];
    const float* Bk     = (const float*)d_in[7];
    const float* Wv     = (const float*)d_in[8];
    const float* Av     = (const float*)d_in[9];
    const float* Bv     = (const float*)d_in[10];
    const float* Wo     = (const float*)d_in[11];
    const float* Ao     = (const float*)d_in[12];
    const float* Bo     = (const float*)d_in[13];
    float* out = (float*)d_out;

    float *Qb, *Kb, *Vb, *AOb, *lq, *lk, *lv, *lo;
    cudaGetSymbolAddress((void**)&Qb, g_Q);
    cudaGetSymbolAddress((void**)&Kb, g_K);
    cudaGetSymbolAddress((void**)&Vb, g_V);
    cudaGetSymbolAddress((void**)&AOb, g_AO);
    cudaGetSymbolAddress((void**)&lq, g_lowQ);
    cudaGetSymbolAddress((void**)&lk, g_lowK);
    cudaGetSymbolAddress((void**)&lv, g_lowV);
    cudaGetSymbolAddress((void**)&lo, g_lowO);

    cudaFuncSetAttribute(attn_kernel, cudaFuncAttributeMaxDynamicSharedMemorySize,
                         ATTN_SMEM_BYTES);

    dim3 gg(D_MODEL / BN, M_TOK / BM);

    low_kernel<<<M_TOK / 4, 128>>>(x, Aq, starts, lq);
    low_kernel<<<M_TOK / 4, 128>>>(x, Ak, starts, lk);
    low_kernel<<<M_TOK / 4, 128>>>(x, Av, starts, lv);

    gemm_lora_mma<<<gg, 256>>>(x, Wq, lq, Bq, starts, Qb);
    gemm_lora_mma<<<gg, 256>>>(x, Wk, lk, Bk, starts, Kb);
    gemm_lora_mma<<<gg, 256>>>(x, Wv, lv, Bv, starts, Vb);

    int npairs = BATCH * SEQ * NUM_HEADS * (D_KV / 2);
    rope_kernel<<<(npairs + 255) / 256, 256>>>(Qb);
    rope_kernel<<<(npairs + 255) / 256, 256>>>(Kb);

    attn_kernel<<<dim3(SEQ / AQT, NUM_HEADS, BATCH), 256, ATTN_SMEM_BYTES>>>(Qb, Kb, Vb, AOb);

    low_kernel<<<M_TOK / 4, 128>>>(AOb, Ao, starts, lo);
    gemm_lora_mma<<<gg, 256>>>(AOb, Wo, lo, Bo, starts, out);
}